// round 7
// baseline (speedup 1.0000x reference)
#include <cuda_runtime.h>
#include <cuda_bf16.h>

// 8x8 DCT-II coefficients, 0.5*cos(pi*(2m+1)k/16) pre-folded (orthonormal).
#define K0 0.3535533905932738f   // 1/(2*sqrt(2))
#define K1 0.4903926402016152f
#define K2 0.4619397662556434f
#define K3 0.4157348061512726f
#define K5 0.2777851165098011f
#define K6 0.1913417161825449f
#define K7 0.0975451610080642f

// In-place 8-point DCT-II (orthonormal), butterfly (even/odd) form.
__device__ __forceinline__ void dct8(float* v) {
    float s0 = v[0] + v[7], s1 = v[1] + v[6], s2 = v[2] + v[5], s3 = v[3] + v[4];
    float d0 = v[0] - v[7], d1 = v[1] - v[6], d2 = v[2] - v[5], d3 = v[3] - v[4];
    float e0 = s0 + s3, e1 = s1 + s2;
    float o0 = s0 - s3, o1 = s1 - s2;
    v[0] = K0 * (e0 + e1);
    v[4] = K0 * (e0 - e1);
    v[2] = K2 * o0 + K6 * o1;
    v[6] = K6 * o0 - K2 * o1;
    v[1] = K1 * d0 + K3 * d1 + K5 * d2 + K7 * d3;
    v[3] = K3 * d0 - K7 * d1 - K1 * d2 - K5 * d3;
    v[5] = K5 * d0 - K1 * d1 + K7 * d2 + K3 * d3;
    v[7] = K7 * d0 - K5 * d1 + K3 * d2 - K1 * d3;
}

// Persistent kernel: one wave of CTAs, each warp grid-strides over 8x32 tiles.
// Warp = 4 horizontally adjacent 8x8 blocks. Thread (j=lane>>2, b=lane&3):
// row j of block b. MLP_p1 = 2 (deeper front-batching regressed via cross-CTA
// L1tex-queue contention in R4). Transpose via padded per-warp SMEM.
__global__ void __launch_bounds__(256)
dct_quant_kernel(const float* __restrict__ x,
                 const float* __restrict__ q,
                 float* __restrict__ out,
                 int nwarps) {
    __shared__ float srq[8][64];         // per-warp 1/q -> no CTA-wide barrier
    __shared__ float tr[8][4][8][9];     // [warp][block][col][row], pad 9

    int wid  = threadIdx.x >> 5;
    int lane = threadIdx.x & 31;
    int j = lane >> 2;   // row within block (becomes horizontal-freq index)
    int b = lane & 3;    // block within tile

    // One-time per-warp q reciprocal table.
    srq[wid][lane]      = 1.0f / q[lane];
    srq[wid][lane + 32] = 1.0f / q[lane + 32];
    __syncwarp();

    const float* sq = srq[wid];
    float* ts = &tr[wid][b][0][0];

    int w      = blockIdx.x * 8 + wid;
    int stride = gridDim.x * 8;

    for (; w < nwarps; w += stride) {
        // tiles: 2048 planes x 16 block-rows x 4 tile-cols
        int img = w >> 6;
        int br  = (w >> 2) & 15;
        int tc  = w & 3;
        long tile = ((long)img << 14) + (br << 10) + (tc << 5);

        const float* base = x + tile + j * 128 + b * 8;

        // Streaming loads (use-once data, evict-first)
        float4 lo = __ldcs(reinterpret_cast<const float4*>(base));
        float4 hi = __ldcs(reinterpret_cast<const float4*>(base + 4));

        float r[8];
        r[0] = lo.x; r[1] = lo.y; r[2] = lo.z; r[3] = lo.w;
        r[4] = hi.x; r[5] = hi.y; r[6] = hi.z; r[7] = hi.w;

        // Row pass (along memory-contiguous dimension)
        dct8(r);

        // Transposed write: tr[wid][b][c][j] = r[c].
        // Banks (8b + 9c + j) mod 32: all 32 distinct for fixed c.
        #pragma unroll
        for (int c = 0; c < 8; c++) ts[c * 9 + j] = r[c];

        __syncwarp();

        // Row-contiguous read: r[i] = R[i][j] (column j).
        // Banks (8b + 9j + i) mod 32: all 32 distinct for fixed i.
        #pragma unroll
        for (int i = 0; i < 8; i++) r[i] = ts[j * 9 + i];

        // Column pass: register index v = vertical freq, j = horizontal freq
        dct8(r);

        // Quantize + round-half-even + clip, store column-oriented (streaming).
        // For fixed v, warp writes one contiguous 128B segment per STG.
        float* obase = out + tile + b * 8 + j;
        #pragma unroll
        for (int v = 0; v < 8; v++) {
            float y = rintf(r[v] * sq[v * 8 + j]);
            y = fminf(fmaxf(y, -128.0f), 127.0f);
            __stcs(obase + v * 128, y);
        }

        // Protect warp-private transpose buffer across iterations.
        __syncwarp();
    }
}

extern "C" void kernel_launch(void* const* d_in, const int* in_sizes, int n_in,
                              void* d_out, int out_size) {
    const float* x = (const float*)d_in[0];
    const float* q = (const float*)d_in[1];
    float* out = (float*)d_out;

    int nelem  = in_sizes[0];         // 33554432
    int nwarps = nelem / 256;         // 131072 tiles (one per warp-iteration)
    int grid   = 148 * 8;             // one full wave of 256-thread CTAs

    dct_quant_kernel<<<grid, 256>>>(x, q, out, nwarps);
}

// round 8
// speedup vs baseline: 1.0957x; 1.0957x over previous
#include <cuda_runtime.h>
#include <cuda_bf16.h>

// 8x8 DCT-II coefficients, 0.5*cos(pi*(2m+1)k/16) pre-folded (orthonormal).
#define K0 0.3535533905932738f   // 1/(2*sqrt(2))
#define K1 0.4903926402016152f
#define K2 0.4619397662556434f
#define K3 0.4157348061512726f
#define K5 0.2777851165098011f
#define K6 0.1913417161825449f
#define K7 0.0975451610080642f

// In-place 8-point DCT-II (orthonormal), butterfly (even/odd) form.
__device__ __forceinline__ void dct8(float* v) {
    float s0 = v[0] + v[7], s1 = v[1] + v[6], s2 = v[2] + v[5], s3 = v[3] + v[4];
    float d0 = v[0] - v[7], d1 = v[1] - v[6], d2 = v[2] - v[5], d3 = v[3] - v[4];
    float e0 = s0 + s3, e1 = s1 + s2;
    float o0 = s0 - s3, o1 = s1 - s2;
    v[0] = K0 * (e0 + e1);
    v[4] = K0 * (e0 - e1);
    v[2] = K2 * o0 + K6 * o1;
    v[6] = K6 * o0 - K2 * o1;
    v[1] = K1 * d0 + K3 * d1 + K5 * d2 + K7 * d3;
    v[3] = K3 * d0 - K7 * d1 - K1 * d2 - K5 * d3;
    v[5] = K5 * d0 - K1 * d1 + K7 * d2 + K3 * d3;
    v[7] = K7 * d0 - K5 * d1 + K3 * d2 - K1 * d3;
}

// Warp = 8x32 tile (4 adjacent 8x8 blocks).
// Loads use line-aligned lane mapping (lane -> row=lane>>3, off16=lane&7):
// each LDG.128 covers 4 FULLY-consumed 128B lines (nL=4, minimal), staged
// through stride-36 smem so each thread recovers its full block-row.
// Compute mapping: thread (j=lane>>2, b=lane&3) owns row j of block b.
// Stores remain col-oriented STG.32 (1 full line per instruction, minimal).
__global__ void __launch_bounds__(256)
dct_quant_kernel(const float* __restrict__ x,
                 const float* __restrict__ q,
                 float* __restrict__ out,
                 int nwarps) {
    __shared__ float srq[8][64];        // per-warp 1/q -> no CTA-wide barrier
    __shared__ float st[8][8][36];      // [warp][row][36]: raw tile, stride 36
    __shared__ float tr[8][4][8][9];    // [warp][block][col][row], pad 9

    int wid  = threadIdx.x >> 5;
    int lane = threadIdx.x & 31;

    int w = blockIdx.x * 8 + wid;
    if (w >= nwarps) return;            // whole warps exit together

    int rr = lane >> 3;                 // load-phase: row group (0..3)
    int oo = lane & 7;                  // load-phase: 16B offset within row
    int j  = lane >> 2;                 // compute-phase: row within block
    int b  = lane & 3;                  // compute-phase: block within tile

    // tiles: 2048 planes x 16 block-rows x 4 tile-cols
    int img = w >> 6;
    int br  = (w >> 2) & 15;
    int tc  = w & 3;
    long tile = ((long)img << 14) + (br << 10) + (tc << 5);

    // Line-aligned streaming loads: rows rr and rr+4 of the tile.
    const float* basel = x + tile + rr * 128 + oo * 4;
    float4 lo = __ldcs(reinterpret_cast<const float4*>(basel));
    float4 hi = __ldcs(reinterpret_cast<const float4*>(basel + 4 * 128));

    // Per-warp q reciprocal init (independent of loads, covered by syncwarp).
    srq[wid][lane]      = 1.0f / q[lane];
    srq[wid][lane + 32] = 1.0f / q[lane + 32];

    // Stage raw tile into smem, stride 36 words per row.
    // STS.128 phase (8 lanes = one row): words r*36 + {0..31} -> banks 0..31.
    float* sw = &st[wid][0][0];
    *reinterpret_cast<float4*>(sw + rr * 36 + oo * 4)       = lo;
    *reinterpret_cast<float4*>(sw + (rr + 4) * 36 + oo * 4) = hi;

    __syncwarp();

    // Each thread reads its full block-row: words j*36 + b*8 + {0..7}.
    // Banks (j*36 + b*8 + k) mod 32 = (4j + 8b + k): all 32 distinct per phase.
    float r[8];
    {
        float4 aa = *reinterpret_cast<const float4*>(sw + j * 36 + b * 8);
        float4 bb = *reinterpret_cast<const float4*>(sw + j * 36 + b * 8 + 4);
        r[0] = aa.x; r[1] = aa.y; r[2] = aa.z; r[3] = aa.w;
        r[4] = bb.x; r[5] = bb.y; r[6] = bb.z; r[7] = bb.w;
    }

    // Row pass (along memory-contiguous dimension)
    dct8(r);

    // Transposed write: tr[wid][b][c][j] = r[c].
    // Banks (8b + 9c + j) mod 32: all 32 distinct for fixed c.
    float* ts = &tr[wid][b][0][0];
    #pragma unroll
    for (int c = 0; c < 8; c++) ts[c * 9 + j] = r[c];

    __syncwarp();

    // Row-contiguous read of transposed data: r[i] = R[i][j] (column j).
    // Banks (8b + 9j + i) mod 32: all 32 distinct for fixed i.
    #pragma unroll
    for (int i = 0; i < 8; i++) r[i] = ts[j * 9 + i];

    // Column pass: register index v = vertical freq, j = horizontal freq
    dct8(r);

    // Quantize + round-half-even + clip, store column-oriented (streaming).
    // For fixed v, warp writes one contiguous, fully-consumed 128B line.
    const float* sq = srq[wid];
    float* obase = out + tile + b * 8 + j;
    #pragma unroll
    for (int v = 0; v < 8; v++) {
        float y = rintf(r[v] * sq[v * 8 + j]);
        y = fminf(fmaxf(y, -128.0f), 127.0f);
        __stcs(obase + v * 128, y);
    }
}

extern "C" void kernel_launch(void* const* d_in, const int* in_sizes, int n_in,
                              void* d_out, int out_size) {
    const float* x = (const float*)d_in[0];
    const float* q = (const float*)d_in[1];
    float* out = (float*)d_out;

    int nelem  = in_sizes[0];         // 33554432
    int nwarps = nelem / 256;         // 131072 tiles (one per warp)
    int grid   = (nwarps + 7) / 8;    // 16384 CTAs of 256 threads

    dct_quant_kernel<<<grid, 256>>>(x, q, out, nwarps);
}